// round 10
// baseline (speedup 1.0000x reference)
#include <cuda_runtime.h>
#include <cuda_bf16.h>

// ChamferLoss R10: break the spill cycle.
// Every prior variant kept colmin[32] in registers, which forces full unroll
// of the column loop -> ptxas hoists/batches the 64-bit LDS loads -> live
// range explosion -> spills (L2 ~39% in R8/R9). Fix: per-warp colmin SLICE in
// SMEM (8 warps = 4 row-blocks x 2 col-halves; slice = 512 floats/warp),
// column loop only unroll-2. p is read straight from global (uniform
// broadcast, prep recomputed per row-group - negligible). Math unchanged:
// u = 0.5*d^2 via packed f32x2 FMA with both half-norms folded into the
// accumulator init; sqrt hoisted outside the mins; row mins via shfl tree +
// SMEM atomicMin on clamped bits; fused deterministic final reduction.

#define NPTS    1024
#define THREADS 256
#define NWARPS  8
#define RG      8
#define CB_MAX  128

typedef unsigned long long ull;

#define PACK2(d, lo, hi) \
    asm("mov.b64 %0, {%1,%2};" : "=l"(d) : "f"(lo), "f"(hi))
#define UNPACK2(lo, hi, s) \
    asm("mov.b64 {%0,%1}, %2;" : "=f"(lo), "=f"(hi) : "l"(s))
#define FMA2(d, a, b, c) \
    asm("fma.rn.f32x2 %0, %1, %2, %3;" : "=l"(d) : "l"(a), "l"(b), "l"(c))
#define ADD2(d, a, b) \
    asm("add.rn.f32x2 %0, %1, %2;" : "=l"(d) : "l"(a), "l"(b))

__device__ float g_partials[CB_MAX];
__device__ int   g_done;   // zero-init; reset by last CTA each run

__global__ __launch_bounds__(THREADS, 1)
void chamfer_pair_kernel(const float* __restrict__ p, const float* __restrict__ q,
                         float* __restrict__ out, int cb_count) {
    __shared__ __align__(16) float qx_s[NPTS], qy_s[NPTS], qz_s[NPTS], qs_s[NPTS];
    __shared__ __align__(16) float cmin_s[NWARPS][NPTS / 2];  // per-warp col slice
    __shared__ unsigned rowmin_sh[NPTS];
    __shared__ float sred[NWARPS];
    __shared__ int sh_last;

    const int cb   = blockIdx.x;
    const int tid  = threadIdx.x;
    const int warp = tid >> 5;
    const int lane = tid & 31;
    const int rb    = warp >> 1;   // row block 0..3  (256 rows each)
    const int chalf = warp & 1;    // column half 0..1 (512 cols each)
    const float INF = __int_as_float(0x7f800000);

    const float4* __restrict__ qp = reinterpret_cast<const float4*>(q) + (size_t)cb * NPTS;
    const float4* __restrict__ pp = reinterpret_cast<const float4*>(p) + (size_t)cb * NPTS;

    // Stage q (SoA + half-norm); init row-min bits.
    for (int i = tid; i < NPTS; i += THREADS) {
        float4 v = qp[i];
        qx_s[i] = v.y; qy_s[i] = v.z; qz_s[i] = v.w;
        qs_s[i] = 0.5f * (v.y * v.y + v.z * v.z + v.w * v.w);
        rowmin_sh[i] = 0x7f800000u;
    }
    // Init private colmin slice.
    for (int k = lane; k < NPTS / 2; k += 32) cmin_s[warp][k] = INF;
    __syncthreads();

    const int colbase0 = chalf * (NPTS / 2);

    #pragma unroll 1
    for (int rg = 0; rg < 32; ++rg) {              // 32 groups of 8 rows
        const int row0 = rb * 256 + rg * RG;
        ull pnx2[RG], pny2[RG], pnz2[RG], psq2[RG];
        float rmin[RG];
        #pragma unroll
        for (int r = 0; r < RG; ++r) {
            float4 u = pp[row0 + r];               // uniform addr -> broadcast
            float a = -u.y, b = -u.z, c = -u.w;
            float s = 0.5f * (u.y * u.y + u.z * u.z + u.w * u.w);
            PACK2(pnx2[r], a, a);
            PACK2(pny2[r], b, b);
            PACK2(pnz2[r], c, c);
            PACK2(psq2[r], s, s);
            rmin[r] = INF;
        }
        #pragma unroll 2
        for (int j2 = 0; j2 < 8; ++j2) {           // 64 cols per j2, 512 total
            const int coff = (j2 << 6) + (lane << 1);
            const int base = colbase0 + coff;
            ull xx2 = *reinterpret_cast<const ull*>(qx_s + base);
            ull yy2 = *reinterpret_cast<const ull*>(qy_s + base);
            ull zz2 = *reinterpret_cast<const ull*>(qz_s + base);
            ull ss2 = *reinterpret_cast<const ull*>(qs_s + base);
            float cl = INF, cm = INF;
            #pragma unroll
            for (int r = 0; r < RG; ++r) {
                ull acc;
                ADD2(acc, ss2, psq2[r]);           // 0.5|q|^2 + 0.5|p|^2 (2 cols)
                FMA2(acc, pnx2[r], xx2, acc);      // - px*qx
                FMA2(acc, pny2[r], yy2, acc);
                FMA2(acc, pnz2[r], zz2, acc);      // acc = 0.5*d2 (2 cols)
                float u0, u1;
                UNPACK2(u0, u1, acc);
                cl = fminf(cl, u0);
                cm = fminf(cm, u1);
                rmin[r] = fminf(rmin[r], fminf(u0, u1));
            }
            // Merge into private SMEM colmin slice (no races, no unroll need).
            float2* cw = reinterpret_cast<float2*>(&cmin_s[warp][coff]);
            float2 o = *cw;
            o.x = fminf(o.x, cl);
            o.y = fminf(o.y, cm);
            *cw = o;
        }
        // Row mins: shfl tree (exact), then SMEM atomicMin on clamped bits.
        #pragma unroll
        for (int r = 0; r < RG; ++r) {
            float m = rmin[r];
            #pragma unroll
            for (int off = 16; off > 0; off >>= 1)
                m = fminf(m, __shfl_xor_sync(0xffffffffu, m, off));
            if (lane == 0)
                atomicMin(&rowmin_sh[row0 + r], __float_as_uint(fmaxf(m, 0.0f)));
        }
    }
    __syncthreads();

    // Per-thread partial: 4 rows + 4 cols each, fixed order.
    float acc = 0.0f;
    for (int i = tid; i < NPTS; i += THREADS)
        acc += sqrtf(2.0f * __uint_as_float(rowmin_sh[i]) + 1e-12f);  // clamped
    for (int c = tid; c < NPTS; c += THREADS) {
        int h = c >> 9, cc = c & 511;
        float m = fminf(fminf(cmin_s[h][cc],     cmin_s[2 + h][cc]),
                        fminf(cmin_s[4 + h][cc], cmin_s[6 + h][cc]));
        acc += sqrtf(2.0f * fmaxf(m, 0.0f) + 1e-12f);
    }
    #pragma unroll
    for (int off = 16; off > 0; off >>= 1)
        acc += __shfl_xor_sync(0xffffffffu, acc, off);
    if (lane == 0) sred[warp] = acc;
    __syncthreads();

    // Per-CTA total + done-ticket.
    if (tid == 0) {
        float total = 0.0f;
        #pragma unroll
        for (int w = 0; w < NWARPS; ++w) total += sred[w];
        g_partials[cb] = total;
        __threadfence();
        int prev = atomicAdd(&g_done, 1);
        sh_last = (prev == cb_count - 1) ? 1 : 0;
    }
    __syncthreads();

    // Last CTA: deterministic fixed-order final reduction over all pairs.
    if (sh_last) {
        __threadfence();
        float v = (tid < cb_count) ? __ldcg(&g_partials[tid]) : 0.0f;
        #pragma unroll
        for (int off = 16; off > 0; off >>= 1)
            v += __shfl_xor_sync(0xffffffffu, v, off);
        if (lane == 0) sred[warp] = v;
        __syncthreads();
        if (tid == 0) {
            float tot = 0.0f;
            #pragma unroll
            for (int w = 0; w < NWARPS; ++w) tot += sred[w];
            out[0] = tot;
            g_done = 0;   // reset for next graph replay
        }
    }
}

extern "C" void kernel_launch(void* const* d_in, const int* in_sizes, int n_in,
                              void* d_out, int out_size) {
    const float* p = (const float*)d_in[0];
    const float* q = (const float*)d_in[1];
    float* out = (float*)d_out;

    int cb = in_sizes[0] / (NPTS * 4);   // = 128 for (2,64,1024,4)
    if (cb > CB_MAX) cb = CB_MAX;

    chamfer_pair_kernel<<<cb, THREADS>>>(p, q, out, cb);
}

// round 11
// speedup vs baseline: 1.3498x; 1.3498x over previous
#include <cuda_runtime.h>
#include <cuda_bf16.h>

// ChamferLoss R11: R10's spill-free layout (colmin slices in SMEM, unroll-2
// column loop, regs=102) x 2-CTA-per-SM residency for latency hiding.
// Grid = 2 CTAs per pair; each CTA owns 512 rows x all 1024 cols.
// __launch_bounds__(256,2) -> reg cap 128, 2 resident CTAs -> 4 warps/SMSP.
// Warp layout: 8 warps = 4 row-blocks(128 rows) x 2 col-halves(512 cols).
// Math: u = 0.5*d^2 via packed f32x2 FMA (norms folded into accumulator
// init); sqrt hoisted outside the mins. Row mins: shfl tree + SMEM atomicMin
// (merges the 2 col-half warps). Column mins: per-warp SMEM slice -> CTA
// merge -> global atomicMax on COMPLEMENTED bits (zero identity; consumer
// resets -> graph-replay safe). Per-pair ticket: 2nd CTA computes the pair
// colsum; global ticket: last CTA does the fixed-order final reduction.
// Fully deterministic.

#define NPTS    1024
#define THREADS 256
#define NWARPS  8
#define RG      8
#define CB_MAX  128

typedef unsigned long long ull;

#define PACK2(d, lo, hi) \
    asm("mov.b64 %0, {%1,%2};" : "=l"(d) : "f"(lo), "f"(hi))
#define UNPACK2(lo, hi, s) \
    asm("mov.b64 {%0,%1}, %2;" : "=f"(lo), "=f"(hi) : "l"(s))
#define FMA2(d, a, b, c) \
    asm("fma.rn.f32x2 %0, %1, %2, %3;" : "=l"(d) : "l"(a), "l"(b), "l"(c))
#define ADD2(d, a, b) \
    asm("add.rn.f32x2 %0, %1, %2;" : "=l"(d) : "l"(a), "l"(b))

__device__ unsigned g_colmin[CB_MAX * NPTS];  // zero-init; key = ~bits(min 0.5d2)
__device__ float    g_rowpart[2 * CB_MAX];
__device__ float    g_pairsum[CB_MAX];
__device__ int      g_paircnt[CB_MAX];        // zero-init; reset by consumer
__device__ int      g_done;                   // zero-init; reset by last CTA

__global__ __launch_bounds__(THREADS, 2)
void chamfer_pair_kernel(const float* __restrict__ p, const float* __restrict__ q,
                         float* __restrict__ out, int cb_count) {
    __shared__ __align__(16) float qx_s[NPTS], qy_s[NPTS], qz_s[NPTS], qs_s[NPTS];
    __shared__ __align__(16) float cmin_s[NWARPS][NPTS / 2];  // per-warp col slice
    __shared__ unsigned rowmin_sh[NPTS / 2];                  // 512 local rows
    __shared__ float sred[NWARPS];
    __shared__ int sh_flag;

    const int cta  = blockIdx.x;
    const int pair = cta >> 1;
    const int half = cta & 1;          // which 512-row half of p
    const int tid  = threadIdx.x;
    const int warp = tid >> 5;
    const int lane = tid & 31;
    const int rb    = warp >> 1;       // row block 0..3 (128 local rows each)
    const int chalf = warp & 1;        // column half 0..1 (512 cols each)
    const float INF = __int_as_float(0x7f800000);

    const float4* __restrict__ qp = reinterpret_cast<const float4*>(q) + (size_t)pair * NPTS;
    const float4* __restrict__ pp = reinterpret_cast<const float4*>(p) + (size_t)pair * NPTS
                                    + half * (NPTS / 2);

    // Stage q (SoA + half-norm); init row-min bits and colmin slices.
    for (int i = tid; i < NPTS; i += THREADS) {
        float4 v = qp[i];
        qx_s[i] = v.y; qy_s[i] = v.z; qz_s[i] = v.w;
        qs_s[i] = 0.5f * (v.y * v.y + v.z * v.z + v.w * v.w);
    }
    for (int i = tid; i < NPTS / 2; i += THREADS) rowmin_sh[i] = 0x7f800000u;
    for (int k = lane; k < NPTS / 2; k += 32) cmin_s[warp][k] = INF;
    __syncthreads();

    const int colbase0 = chalf * (NPTS / 2);

    #pragma unroll 1
    for (int rg = 0; rg < 16; ++rg) {              // 16 groups of 8 local rows
        const int row0 = rb * 128 + rg * RG;       // local row (0..511)
        ull pnx2[RG], pny2[RG], pnz2[RG], psq2[RG];
        float rmin[RG];
        #pragma unroll
        for (int r = 0; r < RG; ++r) {
            float4 u = pp[row0 + r];               // uniform addr -> broadcast
            float a = -u.y, b = -u.z, c = -u.w;
            float s = 0.5f * (u.y * u.y + u.z * u.z + u.w * u.w);
            PACK2(pnx2[r], a, a);
            PACK2(pny2[r], b, b);
            PACK2(pnz2[r], c, c);
            PACK2(psq2[r], s, s);
            rmin[r] = INF;
        }
        #pragma unroll 2
        for (int j2 = 0; j2 < 8; ++j2) {           // 64 cols per j2, 512 total
            const int coff = (j2 << 6) + (lane << 1);
            const int base = colbase0 + coff;
            ull xx2 = *reinterpret_cast<const ull*>(qx_s + base);
            ull yy2 = *reinterpret_cast<const ull*>(qy_s + base);
            ull zz2 = *reinterpret_cast<const ull*>(qz_s + base);
            ull ss2 = *reinterpret_cast<const ull*>(qs_s + base);
            float cl = INF, cm = INF;
            #pragma unroll
            for (int r = 0; r < RG; ++r) {
                ull acc;
                ADD2(acc, ss2, psq2[r]);           // 0.5|q|^2 + 0.5|p|^2 (2 cols)
                FMA2(acc, pnx2[r], xx2, acc);      // - px*qx
                FMA2(acc, pny2[r], yy2, acc);
                FMA2(acc, pnz2[r], zz2, acc);      // acc = 0.5*d2 (2 cols)
                float u0, u1;
                UNPACK2(u0, u1, acc);
                cl = fminf(cl, u0);
                cm = fminf(cm, u1);
                rmin[r] = fminf(rmin[r], fminf(u0, u1));
            }
            float2* cw = reinterpret_cast<float2*>(&cmin_s[warp][coff]);
            float2 o = *cw;
            o.x = fminf(o.x, cl);
            o.y = fminf(o.y, cm);
            *cw = o;                               // private slice: no races
        }
        #pragma unroll
        for (int r = 0; r < RG; ++r) {
            float m = rmin[r];
            #pragma unroll
            for (int off = 16; off > 0; off >>= 1)
                m = fminf(m, __shfl_xor_sync(0xffffffffu, m, off));
            if (lane == 0)   // merge the 2 col-half warps for this row
                atomicMin(&rowmin_sh[row0 + r], __float_as_uint(fmaxf(m, 0.0f)));
        }
    }
    __syncthreads();

    // Row-distance partial for this CTA (512 rows, fixed order).
    float acc = 0.0f;
    for (int i = tid; i < NPTS / 2; i += THREADS)
        acc += sqrtf(2.0f * __uint_as_float(rowmin_sh[i]) + 1e-12f);  // clamped
    #pragma unroll
    for (int off = 16; off > 0; off >>= 1)
        acc += __shfl_xor_sync(0xffffffffu, acc, off);
    if (lane == 0) sred[warp] = acc;

    // CTA-level column-min merge -> one atomicMax per column to global.
    for (int c = tid; c < NPTS; c += THREADS) {
        int h = c >> 9, cc = c & 511;
        float m = fminf(fminf(cmin_s[h][cc],     cmin_s[2 + h][cc]),
                        fminf(cmin_s[4 + h][cc], cmin_s[6 + h][cc]));
        unsigned key = ~__float_as_uint(fmaxf(m, 0.0f));
        atomicMax(&g_colmin[pair * NPTS + c], key);
    }
    __syncthreads();

    if (tid == 0) {
        float s = 0.0f;
        #pragma unroll
        for (int w = 0; w < NWARPS; ++w) s += sred[w];
        g_rowpart[cta] = s;
        __threadfence();                  // order colmin/rowpart before ticket
        int prev = atomicAdd(&g_paircnt[pair], 1);
        sh_flag = (prev == 1) ? 1 : 0;    // 2 CTAs per pair
    }
    __syncthreads();

    // Second CTA of the pair: column sum for the pair (all mins in L2).
    if (sh_flag) {
        __threadfence();
        const uint4* src = reinterpret_cast<const uint4*>(g_colmin) + pair * (NPTS / 4) + tid;
        uint4 k = __ldcg(src);            // bypass L1 -> see both CTAs' atomics
        uint4* dst = reinterpret_cast<uint4*>(g_colmin) + pair * (NPTS / 4) + tid;
        *dst = make_uint4(0u, 0u, 0u, 0u);   // reset for next graph replay
        float s = sqrtf(2.0f * __uint_as_float(~k.x) + 1e-12f)
                + sqrtf(2.0f * __uint_as_float(~k.y) + 1e-12f)
                + sqrtf(2.0f * __uint_as_float(~k.z) + 1e-12f)
                + sqrtf(2.0f * __uint_as_float(~k.w) + 1e-12f);
        #pragma unroll
        for (int off = 16; off > 0; off >>= 1)
            s += __shfl_xor_sync(0xffffffffu, s, off);
        if (lane == 0) sred[warp] = s;
        __syncthreads();
        if (tid == 0) {
            float b = 0.0f;
            #pragma unroll
            for (int w = 0; w < NWARPS; ++w) b += sred[w];
            g_pairsum[pair] = b;
            g_paircnt[pair] = 0;          // reset ticket for next replay
        }
    }

    // Global done-ticket; last CTA does the deterministic final reduction.
    __syncthreads();
    if (tid == 0) {
        __threadfence();
        int prev = atomicAdd(&g_done, 1);
        sh_flag = (prev == 2 * cb_count - 1) ? 1 : 0;
    }
    __syncthreads();
    if (sh_flag) {
        __threadfence();
        float v = 0.0f;
        if (tid < cb_count)     v += __ldcg(&g_pairsum[tid]);
        if (tid < 2 * cb_count) v += __ldcg(&g_rowpart[tid]);
        #pragma unroll
        for (int off = 16; off > 0; off >>= 1)
            v += __shfl_xor_sync(0xffffffffu, v, off);
        if (lane == 0) sred[warp] = v;
        __syncthreads();
        if (tid == 0) {
            float tot = 0.0f;
            #pragma unroll
            for (int w = 0; w < NWARPS; ++w) tot += sred[w];
            out[0] = tot;
            g_done = 0;                   // reset for next graph replay
        }
    }
}

extern "C" void kernel_launch(void* const* d_in, const int* in_sizes, int n_in,
                              void* d_out, int out_size) {
    const float* p = (const float*)d_in[0];
    const float* q = (const float*)d_in[1];
    float* out = (float*)d_out;

    int cb = in_sizes[0] / (NPTS * 4);   // = 128 for (2,64,1024,4)
    if (cb > CB_MAX) cb = CB_MAX;

    chamfer_pair_kernel<<<2 * cb, THREADS>>>(p, q, out, cb);
}